// round 3
// baseline (speedup 1.0000x reference)
#include <cuda_runtime.h>
#include <math_constants.h>

// Problem constants (fixed by the dataset: B=8192, D=256, margin=0.3)
#define BB 8192
#define DD 256
#define TI 128      // rows per block tile
#define TJ 128      // cols per block tile
#define KB 16       // k-chunk
#define NSPLIT 4    // j-range splits
#define MARGIN_F 0.3f

__device__ float g_sq[BB];
__device__ float g_pmax[NSPLIT * BB];
__device__ float g_pmin[NSPLIT * BB];

// Packed f32x2 FMA (SASS FFMA2) — only reachable via PTX on sm_103a.
__device__ __forceinline__ unsigned long long ffma2(
    unsigned long long a, unsigned long long b, unsigned long long c) {
    unsigned long long d;
    asm("fma.rn.f32x2 %0, %1, %2, %3;" : "=l"(d) : "l"(a), "l"(b), "l"(c));
    return d;
}
__device__ __forceinline__ float lo32f(unsigned long long v) {
    return __int_as_float((int)(unsigned)(v & 0xffffffffull));
}
__device__ __forceinline__ float hi32f(unsigned long long v) {
    return __int_as_float((int)(unsigned)(v >> 32));
}

// ---------------------------------------------------------------------------
// 1) Row squared norms.
// ---------------------------------------------------------------------------
__global__ void sq_kernel(const float* __restrict__ x) {
    int row  = blockIdx.x * 8 + (threadIdx.x >> 5);
    int lane = threadIdx.x & 31;
    const float* p = x + (size_t)row * DD;
    float s = 0.f;
    #pragma unroll
    for (int k = lane; k < DD; k += 32) {
        float v = p[k];
        s = fmaf(v, v, s);
    }
    #pragma unroll
    for (int o = 16; o; o >>= 1) s += __shfl_down_sync(0xffffffffu, s, o);
    if (lane == 0) g_sq[row] = s;
}

// ---------------------------------------------------------------------------
// 2) Fused Gram-tile + hard mining, FFMA2 micro-kernel.
//    A tile stored duplicated (float2{v,v}) so broadcast pairs load directly.
//    B pairs come from reading adjacent floats as one 64-bit word.
// ---------------------------------------------------------------------------
__global__ void __launch_bounds__(256, 2)
triplet_main(const float* __restrict__ x, const int* __restrict__ tgt) {
    __shared__ float2 As2[KB][TI];      // duplicated A values
    __shared__ float  Bs[KB][TJ];
    __shared__ float  sSq[TJ];
    __shared__ int    sLbl[TJ];
    __shared__ float  sRedMax[TI][17];
    __shared__ float  sRedMin[TI][17];

    const int tid = threadIdx.x;
    const int tx  = tid & 15;
    const int ty  = tid >> 4;
    const int i0  = blockIdx.x * TI;
    const int spl = blockIdx.y;
    const int jbeg = spl * (BB / NSPLIT);
    const int jend = jbeg + (BB / NSPLIT);

    int lbli[8];
    #pragma unroll
    for (int r = 0; r < 8; r++) lbli[r] = tgt[i0 + ty * 8 + r];

    float maxp[8], minn[8];
    #pragma unroll
    for (int r = 0; r < 8; r++) { maxp[r] = -CUDART_INF_F; minn[r] = CUDART_INF_F; }

    for (int j0 = jbeg; j0 < jend; j0 += TJ) {
        if (tid < TJ) {
            sSq[tid]  = g_sq[j0 + tid];
            sLbl[tid] = tgt[j0 + tid];
        }

        unsigned long long acc2[8][4];
        #pragma unroll
        for (int r = 0; r < 8; r++)
            #pragma unroll
            for (int c = 0; c < 4; c++) acc2[r][c] = 0ull;

        for (int kb = 0; kb < DD; kb += KB) {
            __syncthreads();
            #pragma unroll
            for (int l = 0; l < 2; l++) {
                int idx = tid * 2 + l;          // 0..511
                int row = idx >> 2;             // 0..127
                int kq  = (idx & 3) * 4;        // 0,4,8,12
                float4 va = *(const float4*)(x + (size_t)(i0 + row) * DD + kb + kq);
                As2[kq + 0][row] = make_float2(va.x, va.x);
                As2[kq + 1][row] = make_float2(va.y, va.y);
                As2[kq + 2][row] = make_float2(va.z, va.z);
                As2[kq + 3][row] = make_float2(va.w, va.w);
                float4 vb = *(const float4*)(x + (size_t)(j0 + row) * DD + kb + kq);
                Bs[kq + 0][row] = vb.x; Bs[kq + 1][row] = vb.y;
                Bs[kq + 2][row] = vb.z; Bs[kq + 3][row] = vb.w;
            }
            __syncthreads();

            #pragma unroll
            for (int k = 0; k < KB; k++) {
                const ulonglong2* ap = (const ulonglong2*)&As2[k][ty * 8];
                ulonglong2 av0 = ap[0], av1 = ap[1], av2 = ap[2], av3 = ap[3];
                const ulonglong2* bp = (const ulonglong2*)&Bs[k][tx * 8];
                ulonglong2 bv0 = bp[0], bv1 = bp[1];
                unsigned long long a2[8] = {av0.x, av0.y, av1.x, av1.y,
                                            av2.x, av2.y, av3.x, av3.y};
                unsigned long long b2[4] = {bv0.x, bv0.y, bv1.x, bv1.y};
                #pragma unroll
                for (int r = 0; r < 8; r++)
                    #pragma unroll
                    for (int c = 0; c < 4; c++)
                        acc2[r][c] = ffma2(a2[r], b2[c], acc2[r][c]);
            }
        }

        // Consume: val = sq[j] - 2*dot  (sq[i] cancels everywhere downstream).
        #pragma unroll
        for (int c = 0; c < 4; c++) {
            int j = tx * 8 + c * 2;
            float sj0 = sSq[j],     sj1 = sSq[j + 1];
            int   lj0 = sLbl[j],    lj1 = sLbl[j + 1];
            #pragma unroll
            for (int r = 0; r < 8; r++) {
                float d0 = lo32f(acc2[r][c]);
                float d1 = hi32f(acc2[r][c]);
                float v0 = fmaf(-2.f, d0, sj0);
                float v1 = fmaf(-2.f, d1, sj1);
                if (lj0 == lbli[r]) maxp[r] = fmaxf(maxp[r], v0);
                else                minn[r] = fminf(minn[r], v0);
                if (lj1 == lbli[r]) maxp[r] = fmaxf(maxp[r], v1);
                else                minn[r] = fminf(minn[r], v1);
            }
        }
        __syncthreads();   // protect sSq/sLbl before next tile overwrites
    }

    #pragma unroll
    for (int r = 0; r < 8; r++) {
        sRedMax[ty * 8 + r][tx] = maxp[r];
        sRedMin[ty * 8 + r][tx] = minn[r];
    }
    __syncthreads();
    if (tid < TI) {
        float mp = -CUDART_INF_F, mn = CUDART_INF_F;
        #pragma unroll
        for (int t = 0; t < 16; t++) {
            mp = fmaxf(mp, sRedMax[tid][t]);
            mn = fminf(mn, sRedMin[tid][t]);
        }
        g_pmax[spl * BB + i0 + tid] = mp;
        g_pmin[spl * BB + i0 + tid] = mn;
    }
}

// ---------------------------------------------------------------------------
// 3) Combine splits, compute loss & precision. Single block -> deterministic.
// ---------------------------------------------------------------------------
__global__ void triplet_final(float* __restrict__ out) {
    __shared__ float sL[256];
    __shared__ float sP[256];
    int tid = threadIdx.x;
    float lsum = 0.f, pcnt = 0.f;
    for (int i = tid; i < BB; i += 256) {
        float mp = -CUDART_INF_F, mn = CUDART_INF_F;
        #pragma unroll
        for (int s = 0; s < NSPLIT; s++) {
            mp = fmaxf(mp, g_pmax[s * BB + i]);
            mn = fminf(mn, g_pmin[s * BB + i]);
        }
        float d = mp - mn + MARGIN_F;
        lsum += (d > 0.f) ? d : 0.f;
        pcnt += (mn > mp) ? 1.f : 0.f;
    }
    sL[tid] = lsum; sP[tid] = pcnt;
    __syncthreads();
    #pragma unroll
    for (int o = 128; o; o >>= 1) {
        if (tid < o) { sL[tid] += sL[tid + o]; sP[tid] += sP[tid + o]; }
        __syncthreads();
    }
    if (tid == 0) {
        out[0] = sL[0] / (float)BB;
        out[1] = sP[0] / (float)BB;
    }
}

extern "C" void kernel_launch(void* const* d_in, const int* in_sizes, int n_in,
                              void* d_out, int out_size) {
    const float* x = (const float*)d_in[0];
    const int*   t = (const int*)d_in[1];   // JAX x64-disabled: int32
    float*       o = (float*)d_out;

    sq_kernel<<<BB / 8, 256>>>(x);
    dim3 grid(BB / TI, NSPLIT);
    triplet_main<<<grid, 256>>>(x, t);
    triplet_final<<<1, 256>>>(o);
}

// round 5
// speedup vs baseline: 4.3465x; 4.3465x over previous
#include <cuda_runtime.h>
#include <cuda_bf16.h>
#include <cstdint>
#include <math_constants.h>

#define BB 8192
#define DD 256
#define TI 128
#define TJ 128
#define KC 32              // bf16 k-chunk; hi+lo packed -> 128B smem rows
#define NCH (DD / KC)      // 8
#define MARGIN_F 0.3f

// dynamic smem layout
#define OFF_SQ     0
#define OFF_LBL    512
#define OFF_STAGE  1024
#define STAGE_BYTES 32768          // A tile 16KB + B tile 16KB
#define OFF_B      16384
#define SMEM_DYN   (OFF_STAGE + 2 * STAGE_BYTES)

__device__ __nv_bfloat16 g_xhi[BB * DD];
__device__ __nv_bfloat16 g_xlo[BB * DD];
__device__ float g_sq[BB];
__device__ unsigned int g_maxenc[BB];
__device__ unsigned int g_minenc[BB];

__device__ __forceinline__ uint32_t smem_u32(const void* p) {
    uint32_t a;
    asm("{ .reg .u64 t; cvta.to.shared.u64 t, %1; cvt.u32.u64 %0, t; }" : "=r"(a) : "l"(p));
    return a;
}
__device__ __forceinline__ unsigned enc_f(float f) {
    unsigned u = __float_as_uint(f);
    return (u & 0x80000000u) ? ~u : (u | 0x80000000u);
}
__device__ __forceinline__ float dec_f(unsigned u) {
    return (u & 0x80000000u) ? __uint_as_float(u & 0x7FFFFFFFu) : __uint_as_float(~u);
}
#define CP_ASYNC(dst, src) \
    asm volatile("cp.async.cg.shared.global [%0], [%1], 16;" :: "r"(dst), "l"(src) : "memory")
#define CP_COMMIT() asm volatile("cp.async.commit_group;" ::: "memory")
#define CP_WAIT(n)  asm volatile("cp.async.wait_group " #n ";" ::: "memory")
#define LDSM4(r0,r1,r2,r3,a) \
    asm volatile("ldmatrix.sync.aligned.m8n8.x4.shared.b16 {%0,%1,%2,%3}, [%4];" \
                 : "=r"(r0),"=r"(r1),"=r"(r2),"=r"(r3) : "r"(a))
#define MMA(d,a,b0,b1) \
    asm volatile("mma.sync.aligned.m16n8k16.row.col.f32.bf16.bf16.f32 " \
                 "{%0,%1,%2,%3}, {%4,%5,%6,%7}, {%8,%9}, {%0,%1,%2,%3};" \
                 : "+f"(d[0]),"+f"(d[1]),"+f"(d[2]),"+f"(d[3]) \
                 : "r"(a[0]),"r"(a[1]),"r"(a[2]),"r"(a[3]),"r"(b0),"r"(b1))

// ---------- 0) split fp32 -> bf16 hi/lo ----------
__global__ void prep_kernel(const float* __restrict__ x) {
    int i = blockIdx.x * 256 + threadIdx.x;       // one float4 per thread
    float4 v = ((const float4*)x)[i];
    __nv_bfloat16 h0 = __float2bfloat16(v.x), h1 = __float2bfloat16(v.y);
    __nv_bfloat16 h2 = __float2bfloat16(v.z), h3 = __float2bfloat16(v.w);
    __nv_bfloat16 l0 = __float2bfloat16(v.x - __bfloat162float(h0));
    __nv_bfloat16 l1 = __float2bfloat16(v.y - __bfloat162float(h1));
    __nv_bfloat16 l2 = __float2bfloat16(v.z - __bfloat162float(h2));
    __nv_bfloat16 l3 = __float2bfloat16(v.w - __bfloat162float(h3));
    ((__nv_bfloat162*)g_xhi)[2*i]   = __nv_bfloat162(h0, h1);
    ((__nv_bfloat162*)g_xhi)[2*i+1] = __nv_bfloat162(h2, h3);
    ((__nv_bfloat162*)g_xlo)[2*i]   = __nv_bfloat162(l0, l1);
    ((__nv_bfloat162*)g_xlo)[2*i+1] = __nv_bfloat162(l2, l3);
}

// ---------- 1) row norms (exact fp32) + init mining encodings ----------
__global__ void sq_kernel(const float* __restrict__ x) {
    int row  = blockIdx.x * 8 + (threadIdx.x >> 5);
    int lane = threadIdx.x & 31;
    const float* p = x + (size_t)row * DD;
    float s = 0.f;
    #pragma unroll
    for (int k = lane; k < DD; k += 32) { float v = p[k]; s = fmaf(v, v, s); }
    #pragma unroll
    for (int o = 16; o; o >>= 1) s += __shfl_down_sync(0xffffffffu, s, o);
    if (lane == 0) {
        g_sq[row] = s;
        g_maxenc[row] = 0u;
        g_minenc[row] = 0xFFFFFFFFu;
    }
}

// ---------- 2) bf16 split-MMA Gram tile + fused mining ----------
// smem row layout (per tensor tile, 128 rows x 128B):
//   bytes [0,64)  = hi k0..31 (chunks 0-3), bytes [64,128) = lo (chunks 4-7)
//   chunk swizzle: phys = chunk ^ (row & 7)   -> conflict-free ldmatrix
__global__ void __launch_bounds__(256, 2)
triplet_mma(const int* __restrict__ tgt) {
    extern __shared__ char smem[];
    const uint32_t sb = smem_u32(smem);
    const int tid = threadIdx.x, lane = tid & 31, wid = tid >> 5;
    const int wm = wid >> 2, wn = wid & 3;          // warp tile: rows wm*64, cols wn*32
    const int i0 = blockIdx.x * TI, j0 = blockIdx.y * TJ;

    if (tid < TJ) {
        ((float*)(smem + OFF_SQ))[tid]  = g_sq[j0 + tid];
        ((int*)(smem + OFF_LBL))[tid]   = tgt[j0 + tid];
    }

    float acc[4][4][4];
    #pragma unroll
    for (int mt = 0; mt < 4; mt++)
        #pragma unroll
        for (int nt = 0; nt < 4; nt++)
            #pragma unroll
            for (int e = 0; e < 4; e++) acc[mt][nt][e] = 0.f;

    // ---- async tile loader ----
    auto issue_loads = [&](int c, int st) {
        const uint32_t abase = sb + OFF_STAGE + st * STAGE_BYTES;
        const uint32_t bbase = abase + OFF_B;
        const int kb = c * KC;
        #pragma unroll
        for (int t = 0; t < 2; t++) {
            int idx = t * 256 + tid;           // 0..511
            int row = idx >> 2;                // 0..127
            int ch  = idx & 3;                 // 16B chunk within hi half
            uint32_t dhi = (uint32_t)(( ch      ^ (row & 7)) * 16);
            uint32_t dlo = (uint32_t)(((ch + 4) ^ (row & 7)) * 16);
            const __nv_bfloat16* sAh = g_xhi + (size_t)(i0 + row) * DD + kb + ch * 8;
            const __nv_bfloat16* sAl = g_xlo + (size_t)(i0 + row) * DD + kb + ch * 8;
            const __nv_bfloat16* sBh = g_xhi + (size_t)(j0 + row) * DD + kb + ch * 8;
            const __nv_bfloat16* sBl = g_xlo + (size_t)(j0 + row) * DD + kb + ch * 8;
            CP_ASYNC(abase + row * 128 + dhi, sAh);
            CP_ASYNC(abase + row * 128 + dlo, sAl);
            CP_ASYNC(bbase + row * 128 + dhi, sBh);
            CP_ASYNC(bbase + row * 128 + dlo, sBl);
        }
        CP_COMMIT();
    };

    issue_loads(0, 0);

    for (int c = 0; c < NCH; c++) {
        if (c + 1 < NCH) { issue_loads(c + 1, (c + 1) & 1); CP_WAIT(1); }
        else             { CP_WAIT(0); }
        __syncthreads();

        const uint32_t abase = sb + OFF_STAGE + (c & 1) * STAGE_BYTES;
        const uint32_t bbase = abase + OFF_B;

        #pragma unroll
        for (int ks = 0; ks < 2; ks++) {
            // B fragments: 2 x (hi,lo) ldmatrix.x4 covering n = wn*32 .. +31
            uint32_t bh[8], bl[8];
            #pragma unroll
            for (int p = 0; p < 2; p++) {
                int nrow = wn * 32 + p * 16 + (lane & 7) + ((lane >> 4) << 3);
                int ch   = ks * 2 + ((lane >> 3) & 1);
                uint32_t ah_ = bbase + nrow * 128 + (uint32_t)(( ch      ^ (nrow & 7)) * 16);
                uint32_t al_ = bbase + nrow * 128 + (uint32_t)(((ch + 4) ^ (nrow & 7)) * 16);
                LDSM4(bh[p*4+0], bh[p*4+1], bh[p*4+2], bh[p*4+3], ah_);
                LDSM4(bl[p*4+0], bl[p*4+1], bl[p*4+2], bl[p*4+3], al_);
            }
            #pragma unroll
            for (int mt = 0; mt < 4; mt++) {
                int arow = wm * 64 + mt * 16 + (lane & 15);
                int ch   = ks * 2 + (lane >> 4);
                uint32_t ah_ = abase + arow * 128 + (uint32_t)(( ch      ^ (arow & 7)) * 16);
                uint32_t al_ = abase + arow * 128 + (uint32_t)(((ch + 4) ^ (arow & 7)) * 16);
                uint32_t ahr[4], alr[4];
                LDSM4(ahr[0], ahr[1], ahr[2], ahr[3], ah_);
                LDSM4(alr[0], alr[1], alr[2], alr[3], al_);
                #pragma unroll
                for (int nt = 0; nt < 4; nt++) {
                    uint32_t b0h = bh[(nt >> 1) * 4 + (nt & 1) * 2];
                    uint32_t b1h = bh[(nt >> 1) * 4 + (nt & 1) * 2 + 1];
                    uint32_t b0l = bl[(nt >> 1) * 4 + (nt & 1) * 2];
                    uint32_t b1l = bl[(nt >> 1) * 4 + (nt & 1) * 2 + 1];
                    MMA(acc[mt][nt], ahr, b0h, b1h);   // hi*hi
                    MMA(acc[mt][nt], ahr, b0l, b1l);   // hi*lo
                    MMA(acc[mt][nt], alr, b0h, b1h);   // lo*hi
                }
            }
        }
        __syncthreads();
    }

    // ---- mining epilogue: val = sq[j] - 2*dot  (sq[i] cancels downstream) ----
    const float* sSq  = (const float*)(smem + OFF_SQ);
    const int*   sLbl = (const int*)(smem + OFF_LBL);
    #pragma unroll
    for (int mt = 0; mt < 4; mt++) {
        #pragma unroll
        for (int half = 0; half < 2; half++) {
            int row   = i0 + wm * 64 + mt * 16 + (lane >> 2) + half * 8;
            int mylbl = tgt[row];
            float mp = -CUDART_INF_F, mn = CUDART_INF_F;
            #pragma unroll
            for (int nt = 0; nt < 4; nt++) {
                int jl = wn * 32 + nt * 8 + (lane & 3) * 2;
                float v0 = fmaf(-2.f, acc[mt][nt][half * 2],     sSq[jl]);
                float v1 = fmaf(-2.f, acc[mt][nt][half * 2 + 1], sSq[jl + 1]);
                if (sLbl[jl]     == mylbl) mp = fmaxf(mp, v0); else mn = fminf(mn, v0);
                if (sLbl[jl + 1] == mylbl) mp = fmaxf(mp, v1); else mn = fminf(mn, v1);
            }
            #pragma unroll
            for (int o = 1; o <= 2; o <<= 1) {
                mp = fmaxf(mp, __shfl_xor_sync(0xffffffffu, mp, o));
                mn = fminf(mn, __shfl_xor_sync(0xffffffffu, mn, o));
            }
            if ((lane & 3) == 0) {
                atomicMax(&g_maxenc[row], enc_f(mp));
                atomicMin(&g_minenc[row], enc_f(mn));
            }
        }
    }
}

// ---------- 3) final: decode, loss & precision ----------
__global__ void triplet_final(float* __restrict__ out) {
    __shared__ float sL[256];
    __shared__ float sP[256];
    int tid = threadIdx.x;
    float lsum = 0.f, pcnt = 0.f;
    for (int i = tid; i < BB; i += 256) {
        float mp = dec_f(g_maxenc[i]);
        float mn = dec_f(g_minenc[i]);
        float d = mp - mn + MARGIN_F;        // == dist_ap - dist_an + margin
        lsum += (d > 0.f) ? d : 0.f;
        pcnt += (mn > mp) ? 1.f : 0.f;
    }
    sL[tid] = lsum; sP[tid] = pcnt;
    __syncthreads();
    #pragma unroll
    for (int o = 128; o; o >>= 1) {
        if (tid < o) { sL[tid] += sL[tid + o]; sP[tid] += sP[tid + o]; }
        __syncthreads();
    }
    if (tid == 0) {
        out[0] = sL[0] / (float)BB;
        out[1] = sP[0] / (float)BB;
    }
}

extern "C" void kernel_launch(void* const* d_in, const int* in_sizes, int n_in,
                              void* d_out, int out_size) {
    const float* x = (const float*)d_in[0];
    const int*   t = (const int*)d_in[1];   // JAX x64-disabled: int32
    float*       o = (float*)d_out;

    cudaFuncSetAttribute(triplet_mma, cudaFuncAttributeMaxDynamicSharedMemorySize, SMEM_DYN);

    prep_kernel<<<BB * DD / 4 / 256, 256>>>(x);
    sq_kernel<<<BB / 8, 256>>>(x);
    dim3 grid(BB / TI, BB / TJ);
    triplet_mma<<<grid, 256, SMEM_DYN>>>(t);
    triplet_final<<<1, 256>>>(o);
}

// round 6
// speedup vs baseline: 6.9447x; 1.5978x over previous
#include <cuda_runtime.h>
#include <cuda_bf16.h>
#include <cstdint>
#include <math_constants.h>

#define BB 8192
#define DD 256
#define TI 128
#define TJ 128
#define KC 32              // bf16 k-chunk; hi+lo packed -> 128B smem rows
#define NCH (DD / KC)      // 8
#define NB  (BB / TI)      // 64 block-tiles per dim
#define NTILES (NB * (NB + 1) / 2)   // 2080 upper-triangle tiles
#define MARGIN_F 0.3f

// dynamic smem layout
#define OFF_SQJ    0
#define OFF_LBLJ   512
#define OFF_SQI    1024
#define OFF_LBLI   1536
#define OFF_STAGE  2048
#define STAGE_BYTES 32768          // A tile 16KB + B tile 16KB
#define OFF_B      16384
#define SMEM_DYN   (OFF_STAGE + 2 * STAGE_BYTES)

__device__ __nv_bfloat16 g_xhi[BB * DD];
__device__ __nv_bfloat16 g_xlo[BB * DD];
__device__ float g_sq[BB];
__device__ unsigned int g_maxenc[BB];
__device__ unsigned int g_minenc[BB];

__device__ __forceinline__ uint32_t smem_u32(const void* p) {
    uint32_t a;
    asm("{ .reg .u64 t; cvta.to.shared.u64 t, %1; cvt.u32.u64 %0, t; }" : "=r"(a) : "l"(p));
    return a;
}
__device__ __forceinline__ unsigned enc_f(float f) {
    unsigned u = __float_as_uint(f);
    return (u & 0x80000000u) ? ~u : (u | 0x80000000u);
}
__device__ __forceinline__ float dec_f(unsigned u) {
    return (u & 0x80000000u) ? __uint_as_float(u & 0x7FFFFFFFu) : __uint_as_float(~u);
}
#define CP_ASYNC(dst, src) \
    asm volatile("cp.async.cg.shared.global [%0], [%1], 16;" :: "r"(dst), "l"(src) : "memory")
#define CP_COMMIT() asm volatile("cp.async.commit_group;" ::: "memory")
#define CP_WAIT(n)  asm volatile("cp.async.wait_group " #n ";" ::: "memory")
#define LDSM4(r0,r1,r2,r3,a) \
    asm volatile("ldmatrix.sync.aligned.m8n8.x4.shared.b16 {%0,%1,%2,%3}, [%4];" \
                 : "=r"(r0),"=r"(r1),"=r"(r2),"=r"(r3) : "r"(a))
#define MMA(d,a,b0,b1) \
    asm volatile("mma.sync.aligned.m16n8k16.row.col.f32.bf16.bf16.f32 " \
                 "{%0,%1,%2,%3}, {%4,%5,%6,%7}, {%8,%9}, {%0,%1,%2,%3};" \
                 : "+f"(d[0]),"+f"(d[1]),"+f"(d[2]),"+f"(d[3]) \
                 : "r"(a[0]),"r"(a[1]),"r"(a[2]),"r"(a[3]),"r"(b0),"r"(b1))

// ---------- 0) split fp32 -> bf16 hi/lo ----------
__global__ void prep_kernel(const float* __restrict__ x) {
    int i = blockIdx.x * 256 + threadIdx.x;       // one float4 per thread
    float4 v = ((const float4*)x)[i];
    __nv_bfloat16 h0 = __float2bfloat16(v.x), h1 = __float2bfloat16(v.y);
    __nv_bfloat16 h2 = __float2bfloat16(v.z), h3 = __float2bfloat16(v.w);
    __nv_bfloat16 l0 = __float2bfloat16(v.x - __bfloat162float(h0));
    __nv_bfloat16 l1 = __float2bfloat16(v.y - __bfloat162float(h1));
    __nv_bfloat16 l2 = __float2bfloat16(v.z - __bfloat162float(h2));
    __nv_bfloat16 l3 = __float2bfloat16(v.w - __bfloat162float(h3));
    ((__nv_bfloat162*)g_xhi)[2*i]   = __nv_bfloat162(h0, h1);
    ((__nv_bfloat162*)g_xhi)[2*i+1] = __nv_bfloat162(h2, h3);
    ((__nv_bfloat162*)g_xlo)[2*i]   = __nv_bfloat162(l0, l1);
    ((__nv_bfloat162*)g_xlo)[2*i+1] = __nv_bfloat162(l2, l3);
}

// ---------- 1) row norms (exact fp32) + init mining encodings ----------
__global__ void sq_kernel(const float* __restrict__ x) {
    int row  = blockIdx.x * 8 + (threadIdx.x >> 5);
    int lane = threadIdx.x & 31;
    const float* p = x + (size_t)row * DD;
    float s = 0.f;
    #pragma unroll
    for (int k = lane; k < DD; k += 32) { float v = p[k]; s = fmaf(v, v, s); }
    #pragma unroll
    for (int o = 16; o; o >>= 1) s += __shfl_down_sync(0xffffffffu, s, o);
    if (lane == 0) {
        g_sq[row] = s;
        g_maxenc[row] = 0u;
        g_minenc[row] = 0xFFFFFFFFu;
    }
}

// ---------- 2) bf16 split-MMA Gram tile (upper triangle) + dual mining ----------
__global__ void __launch_bounds__(256, 2)
triplet_mma(const int* __restrict__ tgt) {
    extern __shared__ char smem[];
    const uint32_t sb = smem_u32(smem);
    const int tid = threadIdx.x, lane = tid & 31, wid = tid >> 5;
    const int wm = wid >> 2, wn = wid & 3;          // warp tile: rows wm*64, cols wn*32

    // decode upper-triangle tile index -> (bi, bj), bi <= bj
    int rem = blockIdx.x, bi = 0;
    while (rem >= NB - bi) { rem -= NB - bi; bi++; }
    const int bj = bi + rem;
    const int i0 = bi * TI, j0 = bj * TJ;
    const bool diag = (bi == bj);

    if (tid < TJ) {
        ((float*)(smem + OFF_SQJ))[tid] = g_sq[j0 + tid];
        ((int*)(smem + OFF_LBLJ))[tid]  = tgt[j0 + tid];
    } else {
        int r = tid - TJ;
        ((float*)(smem + OFF_SQI))[r] = g_sq[i0 + r];
        ((int*)(smem + OFF_LBLI))[r]  = tgt[i0 + r];
    }

    float acc[4][4][4];
    #pragma unroll
    for (int mt = 0; mt < 4; mt++)
        #pragma unroll
        for (int nt = 0; nt < 4; nt++)
            #pragma unroll
            for (int e = 0; e < 4; e++) acc[mt][nt][e] = 0.f;

    auto issue_loads = [&](int c, int st) {
        const uint32_t abase = sb + OFF_STAGE + st * STAGE_BYTES;
        const uint32_t bbase = abase + OFF_B;
        const int kb = c * KC;
        #pragma unroll
        for (int t = 0; t < 2; t++) {
            int idx = t * 256 + tid;           // 0..511
            int row = idx >> 2;                // 0..127
            int ch  = idx & 3;
            uint32_t dhi = (uint32_t)(( ch      ^ (row & 7)) * 16);
            uint32_t dlo = (uint32_t)(((ch + 4) ^ (row & 7)) * 16);
            const __nv_bfloat16* sAh = g_xhi + (size_t)(i0 + row) * DD + kb + ch * 8;
            const __nv_bfloat16* sAl = g_xlo + (size_t)(i0 + row) * DD + kb + ch * 8;
            const __nv_bfloat16* sBh = g_xhi + (size_t)(j0 + row) * DD + kb + ch * 8;
            const __nv_bfloat16* sBl = g_xlo + (size_t)(j0 + row) * DD + kb + ch * 8;
            CP_ASYNC(abase + row * 128 + dhi, sAh);
            CP_ASYNC(abase + row * 128 + dlo, sAl);
            CP_ASYNC(bbase + row * 128 + dhi, sBh);
            CP_ASYNC(bbase + row * 128 + dlo, sBl);
        }
        CP_COMMIT();
    };

    issue_loads(0, 0);

    for (int c = 0; c < NCH; c++) {
        if (c + 1 < NCH) { issue_loads(c + 1, (c + 1) & 1); CP_WAIT(1); }
        else             { CP_WAIT(0); }
        __syncthreads();

        const uint32_t abase = sb + OFF_STAGE + (c & 1) * STAGE_BYTES;
        const uint32_t bbase = abase + OFF_B;

        #pragma unroll
        for (int ks = 0; ks < 2; ks++) {
            uint32_t bh[8], bl[8];
            #pragma unroll
            for (int p = 0; p < 2; p++) {
                int nrow = wn * 32 + p * 16 + (lane & 7) + ((lane >> 4) << 3);
                int ch   = ks * 2 + ((lane >> 3) & 1);
                uint32_t ah_ = bbase + nrow * 128 + (uint32_t)(( ch      ^ (nrow & 7)) * 16);
                uint32_t al_ = bbase + nrow * 128 + (uint32_t)(((ch + 4) ^ (nrow & 7)) * 16);
                LDSM4(bh[p*4+0], bh[p*4+1], bh[p*4+2], bh[p*4+3], ah_);
                LDSM4(bl[p*4+0], bl[p*4+1], bl[p*4+2], bl[p*4+3], al_);
            }
            #pragma unroll
            for (int mt = 0; mt < 4; mt++) {
                int arow = wm * 64 + mt * 16 + (lane & 15);
                int ch   = ks * 2 + (lane >> 4);
                uint32_t ah_ = abase + arow * 128 + (uint32_t)(( ch      ^ (arow & 7)) * 16);
                uint32_t al_ = abase + arow * 128 + (uint32_t)(((ch + 4) ^ (arow & 7)) * 16);
                uint32_t ahr[4], alr[4];
                LDSM4(ahr[0], ahr[1], ahr[2], ahr[3], ah_);
                LDSM4(alr[0], alr[1], alr[2], alr[3], al_);
                #pragma unroll
                for (int nt = 0; nt < 4; nt++) {
                    uint32_t b0h = bh[(nt >> 1) * 4 + (nt & 1) * 2];
                    uint32_t b1h = bh[(nt >> 1) * 4 + (nt & 1) * 2 + 1];
                    uint32_t b0l = bl[(nt >> 1) * 4 + (nt & 1) * 2];
                    uint32_t b1l = bl[(nt >> 1) * 4 + (nt & 1) * 2 + 1];
                    MMA(acc[mt][nt], ahr, b0h, b1h);   // hi*hi
                    MMA(acc[mt][nt], ahr, b0l, b1l);   // hi*lo
                    MMA(acc[mt][nt], alr, b0h, b1h);   // lo*hi
                }
            }
        }
        __syncthreads();
    }

    const float* sSqJ  = (const float*)(smem + OFF_SQJ);
    const int*   sLblJ = (const int*)(smem + OFF_LBLJ);
    const float* sSqI  = (const float*)(smem + OFF_SQI);
    const int*   sLblI = (const int*)(smem + OFF_LBLI);

    // ---- row-side mining: row i in bi-range, val = sq[j] - 2*dot ----
    #pragma unroll
    for (int mt = 0; mt < 4; mt++) {
        #pragma unroll
        for (int half = 0; half < 2; half++) {
            int li    = wm * 64 + mt * 16 + (lane >> 2) + half * 8;
            int mylbl = sLblI[li];
            float mp = -CUDART_INF_F, mn = CUDART_INF_F;
            #pragma unroll
            for (int nt = 0; nt < 4; nt++) {
                int jl = wn * 32 + nt * 8 + (lane & 3) * 2;
                float v0 = fmaf(-2.f, acc[mt][nt][half * 2],     sSqJ[jl]);
                float v1 = fmaf(-2.f, acc[mt][nt][half * 2 + 1], sSqJ[jl + 1]);
                if (sLblJ[jl]     == mylbl) mp = fmaxf(mp, v0); else mn = fminf(mn, v0);
                if (sLblJ[jl + 1] == mylbl) mp = fmaxf(mp, v1); else mn = fminf(mn, v1);
            }
            #pragma unroll
            for (int o = 1; o <= 2; o <<= 1) {
                mp = fmaxf(mp, __shfl_xor_sync(0xffffffffu, mp, o));
                mn = fminf(mn, __shfl_xor_sync(0xffffffffu, mn, o));
            }
            if ((lane & 3) == 0) {
                atomicMax(&g_maxenc[i0 + li], enc_f(mp));
                atomicMin(&g_minenc[i0 + li], enc_f(mn));
            }
        }
    }

    // ---- col-side mining (off-diag only): row j in bj-range, val = sq[i] - 2*dot ----
    if (!diag) {
        #pragma unroll
        for (int nt = 0; nt < 4; nt++) {
            #pragma unroll
            for (int e = 0; e < 2; e++) {
                int lj    = wn * 32 + nt * 8 + (lane & 3) * 2 + e;
                int jlbl  = sLblJ[lj];
                float mp = -CUDART_INF_F, mn = CUDART_INF_F;
                #pragma unroll
                for (int mt = 0; mt < 4; mt++) {
                    #pragma unroll
                    for (int half = 0; half < 2; half++) {
                        int li = wm * 64 + mt * 16 + (lane >> 2) + half * 8;
                        float v = fmaf(-2.f, acc[mt][nt][half * 2 + e], sSqI[li]);
                        if (sLblI[li] == jlbl) mp = fmaxf(mp, v);
                        else                   mn = fminf(mn, v);
                    }
                }
                #pragma unroll
                for (int o = 4; o <= 16; o <<= 1) {
                    mp = fmaxf(mp, __shfl_xor_sync(0xffffffffu, mp, o));
                    mn = fminf(mn, __shfl_xor_sync(0xffffffffu, mn, o));
                }
                if (lane < 4) {
                    atomicMax(&g_maxenc[j0 + lj], enc_f(mp));
                    atomicMin(&g_minenc[j0 + lj], enc_f(mn));
                }
            }
        }
    }
}

// ---------- 3) final: decode, loss & precision ----------
__global__ void triplet_final(float* __restrict__ out) {
    __shared__ float sL[1024];
    __shared__ float sP[1024];
    int tid = threadIdx.x;
    float lsum = 0.f, pcnt = 0.f;
    for (int i = tid; i < BB; i += 1024) {
        float mp = dec_f(g_maxenc[i]);
        float mn = dec_f(g_minenc[i]);
        float d = mp - mn + MARGIN_F;        // == dist_ap - dist_an + margin
        lsum += (d > 0.f) ? d : 0.f;
        pcnt += (mn > mp) ? 1.f : 0.f;
    }
    sL[tid] = lsum; sP[tid] = pcnt;
    __syncthreads();
    #pragma unroll
    for (int o = 512; o; o >>= 1) {
        if (tid < o) { sL[tid] += sL[tid + o]; sP[tid] += sP[tid + o]; }
        __syncthreads();
    }
    if (tid == 0) {
        out[0] = sL[0] / (float)BB;
        out[1] = sP[0] / (float)BB;
    }
}

extern "C" void kernel_launch(void* const* d_in, const int* in_sizes, int n_in,
                              void* d_out, int out_size) {
    const float* x = (const float*)d_in[0];
    const int*   t = (const int*)d_in[1];   // JAX x64-disabled: int32
    float*       o = (float*)d_out;

    cudaFuncSetAttribute(triplet_mma, cudaFuncAttributeMaxDynamicSharedMemorySize, SMEM_DYN);

    prep_kernel<<<BB * DD / 4 / 256, 256>>>(x);
    sq_kernel<<<BB / 8, 256>>>(x);
    triplet_mma<<<NTILES, 256, SMEM_DYN>>>(t);
    triplet_final<<<1, 1024>>>(o);
}

// round 7
// speedup vs baseline: 9.5223x; 1.3712x over previous
#include <cuda_runtime.h>
#include <cuda_bf16.h>
#include <cstdint>
#include <math_constants.h>

#define BB 8192
#define DD 256
#define TI 128
#define TJ 128
#define KC 32              // bf16 k-chunk
#define NCH (DD / KC)      // 8
#define NB  (BB / TI)      // 64 block-tiles per dim
#define NTILES (NB * (NB + 1) / 2)   // 2080 upper-triangle tiles
#define MARGIN_F 0.3f

// dynamic smem layout
#define OFF_SQJ    0
#define OFF_LBLJ   512
#define OFF_SQI    1024
#define OFF_LBLI   1536
#define OFF_STAGE  2048
#define STAGE_BYTES 24576          // A tile 16KB (hi+lo) + B tile 8KB (hi only)
#define OFF_B      16384
#define SMEM_DYN   (OFF_STAGE + 2 * STAGE_BYTES)

__device__ __nv_bfloat16 g_xhi[BB * DD];
__device__ __nv_bfloat16 g_xlo[BB * DD];
__device__ float g_sq[BB];
__device__ unsigned int g_maxenc[BB];
__device__ unsigned int g_minenc[BB];

__device__ __forceinline__ uint32_t smem_u32(const void* p) {
    uint32_t a;
    asm("{ .reg .u64 t; cvta.to.shared.u64 t, %1; cvt.u32.u64 %0, t; }" : "=r"(a) : "l"(p));
    return a;
}
__device__ __forceinline__ unsigned enc_f(float f) {
    unsigned u = __float_as_uint(f);
    return (u & 0x80000000u) ? ~u : (u | 0x80000000u);
}
__device__ __forceinline__ float dec_f(unsigned u) {
    return (u & 0x80000000u) ? __uint_as_float(u & 0x7FFFFFFFu) : __uint_as_float(~u);
}
#define CP_ASYNC(dst, src) \
    asm volatile("cp.async.cg.shared.global [%0], [%1], 16;" :: "r"(dst), "l"(src) : "memory")
#define CP_COMMIT() asm volatile("cp.async.commit_group;" ::: "memory")
#define CP_WAIT(n)  asm volatile("cp.async.wait_group " #n ";" ::: "memory")
#define LDSM4(r0,r1,r2,r3,a) \
    asm volatile("ldmatrix.sync.aligned.m8n8.x4.shared.b16 {%0,%1,%2,%3}, [%4];" \
                 : "=r"(r0),"=r"(r1),"=r"(r2),"=r"(r3) : "r"(a))
#define MMA(d,a,b0,b1) \
    asm volatile("mma.sync.aligned.m16n8k16.row.col.f32.bf16.bf16.f32 " \
                 "{%0,%1,%2,%3}, {%4,%5,%6,%7}, {%8,%9}, {%0,%1,%2,%3};" \
                 : "+f"(d[0]),"+f"(d[1]),"+f"(d[2]),"+f"(d[3]) \
                 : "r"(a[0]),"r"(a[1]),"r"(a[2]),"r"(a[3]),"r"(b0),"r"(b1))

// ---------- 0) split fp32 -> bf16 hi/lo, fused row norms + mining init ----------
__global__ void prep_kernel(const float* __restrict__ x) {
    __shared__ float part[8];
    int tid = threadIdx.x, lane = tid & 31, wid = tid >> 5;
    int i = blockIdx.x * 256 + tid;               // one float4 per thread; 4 rows/block
    float4 v = ((const float4*)x)[i];
    __nv_bfloat16 h0 = __float2bfloat16(v.x), h1 = __float2bfloat16(v.y);
    __nv_bfloat16 h2 = __float2bfloat16(v.z), h3 = __float2bfloat16(v.w);
    __nv_bfloat16 l0 = __float2bfloat16(v.x - __bfloat162float(h0));
    __nv_bfloat16 l1 = __float2bfloat16(v.y - __bfloat162float(h1));
    __nv_bfloat16 l2 = __float2bfloat16(v.z - __bfloat162float(h2));
    __nv_bfloat16 l3 = __float2bfloat16(v.w - __bfloat162float(h3));
    ((__nv_bfloat162*)g_xhi)[2*i]   = __nv_bfloat162(h0, h1);
    ((__nv_bfloat162*)g_xhi)[2*i+1] = __nv_bfloat162(h2, h3);
    ((__nv_bfloat162*)g_xlo)[2*i]   = __nv_bfloat162(l0, l1);
    ((__nv_bfloat162*)g_xlo)[2*i+1] = __nv_bfloat162(l2, l3);

    float s = fmaf(v.x, v.x, fmaf(v.y, v.y, fmaf(v.z, v.z, v.w * v.w)));
    #pragma unroll
    for (int o = 16; o; o >>= 1) s += __shfl_down_sync(0xffffffffu, s, o);
    if (lane == 0) part[wid] = s;                 // warp w is entirely within row w/2
    __syncthreads();
    if (tid < 4) {
        int row = blockIdx.x * 4 + tid;
        g_sq[row] = part[tid * 2] + part[tid * 2 + 1];
        g_maxenc[row] = 0u;
        g_minenc[row] = 0xFFFFFFFFu;
    }
}

// ---------- 1) bf16 2-MMA split Gram tile (upper triangle) + dual mining ----------
// A tile: 128 rows x 128B (hi chunks 0-3, lo chunks 4-7), swizzle ch^(row&7).
// B tile: 128 rows x 64B (hi only, chunks 0-3), swizzle ch^((row>>1)&3).
// dot approx = (Ahi + Alo) . Bhi
__global__ void __launch_bounds__(256, 2)
triplet_mma(const int* __restrict__ tgt) {
    extern __shared__ char smem[];
    const uint32_t sb = smem_u32(smem);
    const int tid = threadIdx.x, lane = tid & 31, wid = tid >> 5;
    const int wm = wid >> 2, wn = wid & 3;          // warp tile: rows wm*64, cols wn*32

    // decode upper-triangle tile index -> (bi, bj), bi <= bj
    int rem = blockIdx.x, bi = 0;
    while (rem >= NB - bi) { rem -= NB - bi; bi++; }
    const int bj = bi + rem;
    const int i0 = bi * TI, j0 = bj * TJ;
    const bool diag = (bi == bj);

    if (tid < TJ) {
        ((float*)(smem + OFF_SQJ))[tid] = g_sq[j0 + tid];
        ((int*)(smem + OFF_LBLJ))[tid]  = tgt[j0 + tid];
    } else {
        int r = tid - TJ;
        ((float*)(smem + OFF_SQI))[r] = g_sq[i0 + r];
        ((int*)(smem + OFF_LBLI))[r]  = tgt[i0 + r];
    }

    float acc[4][4][4];
    #pragma unroll
    for (int mt = 0; mt < 4; mt++)
        #pragma unroll
        for (int nt = 0; nt < 4; nt++)
            #pragma unroll
            for (int e = 0; e < 4; e++) acc[mt][nt][e] = 0.f;

    auto issue_loads = [&](int c, int st) {
        const uint32_t abase = sb + OFF_STAGE + st * STAGE_BYTES;
        const uint32_t bbase = abase + OFF_B;
        const int kb = c * KC;
        // A: hi + lo, 128 rows x 4 chunks each
        #pragma unroll
        for (int t = 0; t < 2; t++) {
            int idx = t * 256 + tid;           // 0..511
            int row = idx >> 2;                // 0..127
            int ch  = idx & 3;
            uint32_t dhi = (uint32_t)(( ch      ^ (row & 7)) * 16);
            uint32_t dlo = (uint32_t)(((ch + 4) ^ (row & 7)) * 16);
            const __nv_bfloat16* sAh = g_xhi + (size_t)(i0 + row) * DD + kb + ch * 8;
            const __nv_bfloat16* sAl = g_xlo + (size_t)(i0 + row) * DD + kb + ch * 8;
            CP_ASYNC(abase + row * 128 + dhi, sAh);
            CP_ASYNC(abase + row * 128 + dlo, sAl);
        }
        // B: hi only, 128 rows x 4 chunks, 64B rows
        #pragma unroll
        for (int t = 0; t < 2; t++) {
            int idx = t * 256 + tid;           // 0..511
            int row = idx >> 2;
            int ch  = idx & 3;
            uint32_t d = (uint32_t)((ch ^ ((row >> 1) & 3)) * 16);
            const __nv_bfloat16* sBh = g_xhi + (size_t)(j0 + row) * DD + kb + ch * 8;
            CP_ASYNC(bbase + row * 64 + d, sBh);
        }
        CP_COMMIT();
    };

    issue_loads(0, 0);

    for (int c = 0; c < NCH; c++) {
        if (c + 1 < NCH) { issue_loads(c + 1, (c + 1) & 1); CP_WAIT(1); }
        else             { CP_WAIT(0); }
        __syncthreads();

        const uint32_t abase = sb + OFF_STAGE + (c & 1) * STAGE_BYTES;
        const uint32_t bbase = abase + OFF_B;

        #pragma unroll
        for (int ks = 0; ks < 2; ks++) {
            uint32_t bh[8];
            #pragma unroll
            for (int p = 0; p < 2; p++) {
                int nrow = wn * 32 + p * 16 + (lane & 7) + ((lane >> 4) << 3);
                int ch   = ks * 2 + ((lane >> 3) & 1);
                uint32_t a_ = bbase + nrow * 64 + (uint32_t)((ch ^ ((nrow >> 1) & 3)) * 16);
                LDSM4(bh[p*4+0], bh[p*4+1], bh[p*4+2], bh[p*4+3], a_);
            }
            #pragma unroll
            for (int mt = 0; mt < 4; mt++) {
                int arow = wm * 64 + mt * 16 + (lane & 15);
                int ch   = ks * 2 + (lane >> 4);
                uint32_t ah_ = abase + arow * 128 + (uint32_t)(( ch      ^ (arow & 7)) * 16);
                uint32_t al_ = abase + arow * 128 + (uint32_t)(((ch + 4) ^ (arow & 7)) * 16);
                uint32_t ahr[4], alr[4];
                LDSM4(ahr[0], ahr[1], ahr[2], ahr[3], ah_);
                LDSM4(alr[0], alr[1], alr[2], alr[3], al_);
                #pragma unroll
                for (int nt = 0; nt < 4; nt++) {
                    uint32_t b0 = bh[(nt >> 1) * 4 + (nt & 1) * 2];
                    uint32_t b1 = bh[(nt >> 1) * 4 + (nt & 1) * 2 + 1];
                    MMA(acc[mt][nt], ahr, b0, b1);   // hi_A * hi_B
                    MMA(acc[mt][nt], alr, b0, b1);   // lo_A * hi_B
                }
            }
        }
        __syncthreads();
    }

    const float* sSqJ  = (const float*)(smem + OFF_SQJ);
    const int*   sLblJ = (const int*)(smem + OFF_LBLJ);
    const float* sSqI  = (const float*)(smem + OFF_SQI);
    const int*   sLblI = (const int*)(smem + OFF_LBLI);

    // ---- row-side mining: row i in bi-range, val = sq[j] - 2*dot ----
    #pragma unroll
    for (int mt = 0; mt < 4; mt++) {
        #pragma unroll
        for (int half = 0; half < 2; half++) {
            int li    = wm * 64 + mt * 16 + (lane >> 2) + half * 8;
            int mylbl = sLblI[li];
            float mp = -CUDART_INF_F, mn = CUDART_INF_F;
            #pragma unroll
            for (int nt = 0; nt < 4; nt++) {
                int jl = wn * 32 + nt * 8 + (lane & 3) * 2;
                float v0 = fmaf(-2.f, acc[mt][nt][half * 2],     sSqJ[jl]);
                float v1 = fmaf(-2.f, acc[mt][nt][half * 2 + 1], sSqJ[jl + 1]);
                if (sLblJ[jl]     == mylbl) mp = fmaxf(mp, v0); else mn = fminf(mn, v0);
                if (sLblJ[jl + 1] == mylbl) mp = fmaxf(mp, v1); else mn = fminf(mn, v1);
            }
            #pragma unroll
            for (int o = 1; o <= 2; o <<= 1) {
                mp = fmaxf(mp, __shfl_xor_sync(0xffffffffu, mp, o));
                mn = fminf(mn, __shfl_xor_sync(0xffffffffu, mn, o));
            }
            if ((lane & 3) == 0) {
                atomicMax(&g_maxenc[i0 + li], enc_f(mp));
                atomicMin(&g_minenc[i0 + li], enc_f(mn));
            }
        }
    }

    // ---- col-side mining (off-diag only): row j in bj-range, val = sq[i] - 2*dot ----
    if (!diag) {
        #pragma unroll
        for (int nt = 0; nt < 4; nt++) {
            #pragma unroll
            for (int e = 0; e < 2; e++) {
                int lj    = wn * 32 + nt * 8 + (lane & 3) * 2 + e;
                int jlbl  = sLblJ[lj];
                float mp = -CUDART_INF_F, mn = CUDART_INF_F;
                #pragma unroll
                for (int mt = 0; mt < 4; mt++) {
                    #pragma unroll
                    for (int half = 0; half < 2; half++) {
                        int li = wm * 64 + mt * 16 + (lane >> 2) + half * 8;
                        float v = fmaf(-2.f, acc[mt][nt][half * 2 + e], sSqI[li]);
                        if (sLblI[li] == jlbl) mp = fmaxf(mp, v);
                        else                   mn = fminf(mn, v);
                    }
                }
                #pragma unroll
                for (int o = 4; o <= 16; o <<= 1) {
                    mp = fmaxf(mp, __shfl_xor_sync(0xffffffffu, mp, o));
                    mn = fminf(mn, __shfl_xor_sync(0xffffffffu, mn, o));
                }
                if (lane < 4) {
                    atomicMax(&g_maxenc[j0 + lj], enc_f(mp));
                    atomicMin(&g_minenc[j0 + lj], enc_f(mn));
                }
            }
        }
    }
}

// ---------- 2) final: decode, loss & precision (shuffle tree) ----------
__global__ void triplet_final(float* __restrict__ out) {
    __shared__ float wl[32], wp[32];
    int tid = threadIdx.x, lane = tid & 31, wid = tid >> 5;
    float lsum = 0.f, pcnt = 0.f;
    for (int i = tid; i < BB; i += 1024) {
        float mp = dec_f(g_maxenc[i]);
        float mn = dec_f(g_minenc[i]);
        float d = mp - mn + MARGIN_F;        // == dist_ap - dist_an + margin
        lsum += (d > 0.f) ? d : 0.f;
        pcnt += (mn > mp) ? 1.f : 0.f;
    }
    #pragma unroll
    for (int o = 16; o; o >>= 1) {
        lsum += __shfl_down_sync(0xffffffffu, lsum, o);
        pcnt += __shfl_down_sync(0xffffffffu, pcnt, o);
    }
    if (lane == 0) { wl[wid] = lsum; wp[wid] = pcnt; }
    __syncthreads();
    if (wid == 0) {
        float l = wl[lane], p = wp[lane];
        #pragma unroll
        for (int o = 16; o; o >>= 1) {
            l += __shfl_down_sync(0xffffffffu, l, o);
            p += __shfl_down_sync(0xffffffffu, p, o);
        }
        if (lane == 0) {
            out[0] = l / (float)BB;
            out[1] = p / (float)BB;
        }
    }
}

extern "C" void kernel_launch(void* const* d_in, const int* in_sizes, int n_in,
                              void* d_out, int out_size) {
    const float* x = (const float*)d_in[0];
    const int*   t = (const int*)d_in[1];   // JAX x64-disabled: int32
    float*       o = (float*)d_out;

    cudaFuncSetAttribute(triplet_mma, cudaFuncAttributeMaxDynamicSharedMemorySize, SMEM_DYN);

    prep_kernel<<<BB * DD / 4 / 256, 256>>>(x);
    triplet_mma<<<NTILES, 256, SMEM_DYN>>>(t);
    triplet_final<<<1, 1024>>>(o);
}

// round 8
// speedup vs baseline: 13.1402x; 1.3799x over previous
#include <cuda_runtime.h>
#include <cuda_fp16.h>
#include <cuda_bf16.h>
#include <cstdint>
#include <math_constants.h>

#define BB 8192
#define DD 256
#define TI 128
#define TJ 128
#define KC 32              // fp16 k-chunk = 64B rows
#define NCH (DD / KC)      // 8
#define NB  (BB / TI)      // 64
#define NTILES (NB * (NB + 1) / 2)   // 2080 upper-triangle tiles
#define GRID 296           // persistent: 148 SMs x 2 CTAs
#define MARGIN_F 0.3f

// dynamic smem layout
#define OFF_SQJ    0
#define OFF_LBLJ   512
#define OFF_SQI    1024
#define OFF_LBLI   1536
#define OFF_STAGE  2048
#define STAGE_BYTES 16384          // A tile 8KB + B tile 8KB (fp16)
#define OFF_B      8192
#define SMEM_DYN   (OFF_STAGE + 2 * STAGE_BYTES)

__device__ __half g_xh[BB * DD];
__device__ float g_sq[BB];
__device__ unsigned int g_maxenc[BB];
__device__ unsigned int g_minenc[BB];

__device__ __forceinline__ uint32_t smem_u32(const void* p) {
    uint32_t a;
    asm("{ .reg .u64 t; cvta.to.shared.u64 t, %1; cvt.u32.u64 %0, t; }" : "=r"(a) : "l"(p));
    return a;
}
__device__ __forceinline__ unsigned enc_f(float f) {
    unsigned u = __float_as_uint(f);
    return (u & 0x80000000u) ? ~u : (u | 0x80000000u);
}
__device__ __forceinline__ float dec_f(unsigned u) {
    return (u & 0x80000000u) ? __uint_as_float(u & 0x7FFFFFFFu) : __uint_as_float(~u);
}
#define CP_ASYNC(dst, src) \
    asm volatile("cp.async.cg.shared.global [%0], [%1], 16;" :: "r"(dst), "l"(src) : "memory")
#define CP_COMMIT() asm volatile("cp.async.commit_group;" ::: "memory")
#define CP_WAIT(n)  asm volatile("cp.async.wait_group " #n ";" ::: "memory")
#define LDSM4(r0,r1,r2,r3,a) \
    asm volatile("ldmatrix.sync.aligned.m8n8.x4.shared.b16 {%0,%1,%2,%3}, [%4];" \
                 : "=r"(r0),"=r"(r1),"=r"(r2),"=r"(r3) : "r"(a))
#define MMAH(d,a,b0,b1) \
    asm volatile("mma.sync.aligned.m16n8k16.row.col.f32.f16.f16.f32 " \
                 "{%0,%1,%2,%3}, {%4,%5,%6,%7}, {%8,%9}, {%0,%1,%2,%3};" \
                 : "+f"(d[0]),"+f"(d[1]),"+f"(d[2]),"+f"(d[3]) \
                 : "r"(a[0]),"r"(a[1]),"r"(a[2]),"r"(a[3]),"r"(b0),"r"(b1))

// ---------- 0) fp32 -> fp16, fused row norms + mining init ----------
__global__ void prep_kernel(const float* __restrict__ x) {
    __shared__ float part[8];
    int tid = threadIdx.x, lane = tid & 31, wid = tid >> 5;
    int i = blockIdx.x * 256 + tid;               // one float4 per thread; 4 rows/block
    float4 v = ((const float4*)x)[i];
    __half2 p0 = __floats2half2_rn(v.x, v.y);
    __half2 p1 = __floats2half2_rn(v.z, v.w);
    ((__half2*)g_xh)[2*i]   = p0;
    ((__half2*)g_xh)[2*i+1] = p1;

    float s = fmaf(v.x, v.x, fmaf(v.y, v.y, fmaf(v.z, v.z, v.w * v.w)));
    #pragma unroll
    for (int o = 16; o; o >>= 1) s += __shfl_down_sync(0xffffffffu, s, o);
    if (lane == 0) part[wid] = s;                 // warp w lies within row w/2
    __syncthreads();
    if (tid < 4) {
        int row = blockIdx.x * 4 + tid;
        g_sq[row] = part[tid * 2] + part[tid * 2 + 1];
        g_maxenc[row] = 0u;
        g_minenc[row] = 0xFFFFFFFFu;
    }
}

// ---------- 1) fp16 single-MMA Gram tiles (upper triangle, persistent) ----------
// Tiles: 128 rows x 64B, chunk swizzle ch ^ ((row>>1)&3)  -> conflict-free ldmatrix.
__global__ void __launch_bounds__(256, 2)
triplet_mma(const int* __restrict__ tgt) {
    extern __shared__ char smem[];
    const uint32_t sb = smem_u32(smem);
    const int tid = threadIdx.x, lane = tid & 31, wid = tid >> 5;
    const int wm = wid >> 2, wn = wid & 3;          // warp tile: rows wm*64, cols wn*32

    for (int tile = blockIdx.x; tile < NTILES; tile += GRID) {
        int rem = tile, bi = 0;
        while (rem >= NB - bi) { rem -= NB - bi; bi++; }
        const int bj = bi + rem;
        const int i0 = bi * TI, j0 = bj * TJ;
        const bool diag = (bi == bj);

        __syncthreads();   // previous tile's epilogue done before smem reuse
        if (tid < TJ) {
            ((float*)(smem + OFF_SQJ))[tid] = g_sq[j0 + tid];
            ((int*)(smem + OFF_LBLJ))[tid]  = tgt[j0 + tid];
        } else {
            int r = tid - TJ;
            ((float*)(smem + OFF_SQI))[r] = g_sq[i0 + r];
            ((int*)(smem + OFF_LBLI))[r]  = tgt[i0 + r];
        }

        float acc[4][4][4];
        #pragma unroll
        for (int mt = 0; mt < 4; mt++)
            #pragma unroll
            for (int nt = 0; nt < 4; nt++)
                #pragma unroll
                for (int e = 0; e < 4; e++) acc[mt][nt][e] = 0.f;

        auto issue_loads = [&](int c, int st) {
            const uint32_t abase = sb + OFF_STAGE + st * STAGE_BYTES;
            const uint32_t bbase = abase + OFF_B;
            const int kb = c * KC;
            #pragma unroll
            for (int t = 0; t < 2; t++) {
                int idx = t * 256 + tid;           // 0..511
                int row = idx >> 2;                // 0..127
                int ch  = idx & 3;
                uint32_t d = (uint32_t)((ch ^ ((row >> 1) & 3)) * 16);
                const __half* sA = g_xh + (size_t)(i0 + row) * DD + kb + ch * 8;
                const __half* sB = g_xh + (size_t)(j0 + row) * DD + kb + ch * 8;
                CP_ASYNC(abase + row * 64 + d, sA);
                CP_ASYNC(bbase + row * 64 + d, sB);
            }
            CP_COMMIT();
        };

        issue_loads(0, 0);

        for (int c = 0; c < NCH; c++) {
            if (c + 1 < NCH) { issue_loads(c + 1, (c + 1) & 1); CP_WAIT(1); }
            else             { CP_WAIT(0); }
            __syncthreads();

            const uint32_t abase = sb + OFF_STAGE + (c & 1) * STAGE_BYTES;
            const uint32_t bbase = abase + OFF_B;

            #pragma unroll
            for (int ks = 0; ks < 2; ks++) {
                uint32_t bh[8];
                #pragma unroll
                for (int p = 0; p < 2; p++) {
                    int nrow = wn * 32 + p * 16 + (lane & 7) + ((lane >> 4) << 3);
                    int ch   = ks * 2 + ((lane >> 3) & 1);
                    uint32_t a_ = bbase + nrow * 64 + (uint32_t)((ch ^ ((nrow >> 1) & 3)) * 16);
                    LDSM4(bh[p*4+0], bh[p*4+1], bh[p*4+2], bh[p*4+3], a_);
                }
                #pragma unroll
                for (int mt = 0; mt < 4; mt++) {
                    int arow = wm * 64 + mt * 16 + (lane & 15);
                    int ch   = ks * 2 + (lane >> 4);
                    uint32_t a_ = abase + arow * 64 + (uint32_t)((ch ^ ((arow >> 1) & 3)) * 16);
                    uint32_t ar[4];
                    LDSM4(ar[0], ar[1], ar[2], ar[3], a_);
                    #pragma unroll
                    for (int nt = 0; nt < 4; nt++) {
                        uint32_t b0 = bh[(nt >> 1) * 4 + (nt & 1) * 2];
                        uint32_t b1 = bh[(nt >> 1) * 4 + (nt & 1) * 2 + 1];
                        MMAH(acc[mt][nt], ar, b0, b1);
                    }
                }
            }
            __syncthreads();
        }

        const float* sSqJ  = (const float*)(smem + OFF_SQJ);
        const int*   sLblJ = (const int*)(smem + OFF_LBLJ);
        const float* sSqI  = (const float*)(smem + OFF_SQI);
        const int*   sLblI = (const int*)(smem + OFF_LBLI);

        // ---- row-side mining: val = sq[j] - 2*dot ----
        #pragma unroll
        for (int mt = 0; mt < 4; mt++) {
            #pragma unroll
            for (int half = 0; half < 2; half++) {
                int li    = wm * 64 + mt * 16 + (lane >> 2) + half * 8;
                int mylbl = sLblI[li];
                float mp = -CUDART_INF_F, mn = CUDART_INF_F;
                #pragma unroll
                for (int nt = 0; nt < 4; nt++) {
                    int jl = wn * 32 + nt * 8 + (lane & 3) * 2;
                    float v0 = fmaf(-2.f, acc[mt][nt][half * 2],     sSqJ[jl]);
                    float v1 = fmaf(-2.f, acc[mt][nt][half * 2 + 1], sSqJ[jl + 1]);
                    if (sLblJ[jl]     == mylbl) mp = fmaxf(mp, v0); else mn = fminf(mn, v0);
                    if (sLblJ[jl + 1] == mylbl) mp = fmaxf(mp, v1); else mn = fminf(mn, v1);
                }
                #pragma unroll
                for (int o = 1; o <= 2; o <<= 1) {
                    mp = fmaxf(mp, __shfl_xor_sync(0xffffffffu, mp, o));
                    mn = fminf(mn, __shfl_xor_sync(0xffffffffu, mn, o));
                }
                if ((lane & 3) == 0) {
                    atomicMax(&g_maxenc[i0 + li], enc_f(mp));
                    atomicMin(&g_minenc[i0 + li], enc_f(mn));
                }
            }
        }

        // ---- col-side mining (off-diag only): val = sq[i] - 2*dot ----
        if (!diag) {
            #pragma unroll
            for (int nt = 0; nt < 4; nt++) {
                #pragma unroll
                for (int e = 0; e < 2; e++) {
                    int lj    = wn * 32 + nt * 8 + (lane & 3) * 2 + e;
                    int jlbl  = sLblJ[lj];
                    float mp = -CUDART_INF_F, mn = CUDART_INF_F;
                    #pragma unroll
                    for (int mt = 0; mt < 4; mt++) {
                        #pragma unroll
                        for (int half = 0; half < 2; half++) {
                            int li = wm * 64 + mt * 16 + (lane >> 2) + half * 8;
                            float v = fmaf(-2.f, acc[mt][nt][half * 2 + e], sSqI[li]);
                            if (sLblI[li] == jlbl) mp = fmaxf(mp, v);
                            else                   mn = fminf(mn, v);
                        }
                    }
                    #pragma unroll
                    for (int o = 4; o <= 16; o <<= 1) {
                        mp = fmaxf(mp, __shfl_xor_sync(0xffffffffu, mp, o));
                        mn = fminf(mn, __shfl_xor_sync(0xffffffffu, mn, o));
                    }
                    if (lane < 4) {
                        atomicMax(&g_maxenc[j0 + lj], enc_f(mp));
                        atomicMin(&g_minenc[j0 + lj], enc_f(mn));
                    }
                }
            }
        }
    }
}

// ---------- 2) final: decode, loss & precision (shuffle tree) ----------
__global__ void triplet_final(float* __restrict__ out) {
    __shared__ float wl[32], wp[32];
    int tid = threadIdx.x, lane = tid & 31, wid = tid >> 5;
    float lsum = 0.f, pcnt = 0.f;
    for (int i = tid; i < BB; i += 1024) {
        float mp = dec_f(g_maxenc[i]);
        float mn = dec_f(g_minenc[i]);
        float d = mp - mn + MARGIN_F;        // == dist_ap - dist_an + margin
        lsum += (d > 0.f) ? d : 0.f;
        pcnt += (mn > mp) ? 1.f : 0.f;
    }
    #pragma unroll
    for (int o = 16; o; o >>= 1) {
        lsum += __shfl_down_sync(0xffffffffu, lsum, o);
        pcnt += __shfl_down_sync(0xffffffffu, pcnt, o);
    }
    if (lane == 0) { wl[wid] = lsum; wp[wid] = pcnt; }
    __syncthreads();
    if (wid == 0) {
        float l = wl[lane], p = wp[lane];
        #pragma unroll
        for (int o = 16; o; o >>= 1) {
            l += __shfl_down_sync(0xffffffffu, l, o);
            p += __shfl_down_sync(0xffffffffu, p, o);
        }
        if (lane == 0) {
            out[0] = l / (float)BB;
            out[1] = p / (float)BB;
        }
    }
}

extern "C" void kernel_launch(void* const* d_in, const int* in_sizes, int n_in,
                              void* d_out, int out_size) {
    const float* x = (const float*)d_in[0];
    const int*   t = (const int*)d_in[1];   // JAX x64-disabled: int32
    float*       o = (float*)d_out;

    cudaFuncSetAttribute(triplet_mma, cudaFuncAttributeMaxDynamicSharedMemorySize, SMEM_DYN);

    prep_kernel<<<BB * DD / 4 / 256, 256>>>(x);
    triplet_mma<<<GRID, 256, SMEM_DYN>>>(t);
    triplet_final<<<1, 1024>>>(o);
}

// round 9
// speedup vs baseline: 13.4355x; 1.0225x over previous
#include <cuda_runtime.h>
#include <cuda_fp16.h>
#include <cstdint>
#include <math_constants.h>

#define BB 8192
#define DD 256
#define TI 128
#define TJ 128
#define KC 64              // fp16 k-chunk = 128B rows
#define NCH (DD / KC)      // 4
#define NB  (BB / TI)      // 64
#define NTILES (NB * (NB + 1) / 2)   // 2080
#define GRID 296           // persistent: 148 SMs x 2 CTAs
#define MARGIN_F 0.3f

// dynamic smem layout
#define OFF_SQJ    0
#define OFF_LBLJ   512
#define OFF_SQI    1024
#define OFF_LBLI   1536
#define OFF_STAGE  2048
#define STAGE_BYTES 32768          // A tile 16KB + B tile 16KB
#define OFF_B      16384
#define SMEM_DYN   (OFF_STAGE + 2 * STAGE_BYTES)

__device__ __half g_xh[BB * DD];
__device__ float g_sq[BB];
__device__ unsigned int g_maxenc[BB];
__device__ unsigned int g_minenc[BB];

__device__ __forceinline__ uint32_t smem_u32(const void* p) {
    uint32_t a;
    asm("{ .reg .u64 t; cvta.to.shared.u64 t, %1; cvt.u32.u64 %0, t; }" : "=r"(a) : "l"(p));
    return a;
}
__device__ __forceinline__ unsigned enc_f(float f) {
    unsigned u = __float_as_uint(f);
    return (u & 0x80000000u) ? ~u : (u | 0x80000000u);
}
__device__ __forceinline__ float dec_f(unsigned u) {
    return (u & 0x80000000u) ? __uint_as_float(u & 0x7FFFFFFFu) : __uint_as_float(~u);
}
#define CP_ASYNC(dst, src) \
    asm volatile("cp.async.cg.shared.global [%0], [%1], 16;" :: "r"(dst), "l"(src) : "memory")
#define CP_COMMIT() asm volatile("cp.async.commit_group;" ::: "memory")
#define CP_WAIT(n)  asm volatile("cp.async.wait_group " #n ";" ::: "memory")
#define LDSM4(r0,r1,r2,r3,a) \
    asm volatile("ldmatrix.sync.aligned.m8n8.x4.shared.b16 {%0,%1,%2,%3}, [%4];" \
                 : "=r"(r0),"=r"(r1),"=r"(r2),"=r"(r3) : "r"(a))
#define MMAH(d,a,b0,b1) \
    asm volatile("mma.sync.aligned.m16n8k16.row.col.f32.f16.f16.f32 " \
                 "{%0,%1,%2,%3}, {%4,%5,%6,%7}, {%8,%9}, {%0,%1,%2,%3};" \
                 : "+f"(d[0]),"+f"(d[1]),"+f"(d[2]),"+f"(d[3]) \
                 : "r"(a[0]),"r"(a[1]),"r"(a[2]),"r"(a[3]),"r"(b0),"r"(b1))

// ---------- 0) fp32 -> fp16, fused row norms + mining init (2 float4/thread) ----------
__global__ void prep_kernel(const float* __restrict__ x) {
    __shared__ float part[16];
    int tid = threadIdx.x, lane = tid & 31, wid = tid >> 5;
    float s[2];
    #pragma unroll
    for (int h = 0; h < 2; h++) {
        int i = blockIdx.x * 512 + h * 256 + tid;      // float4 index
        float4 v = ((const float4*)x)[i];
        ((__half2*)g_xh)[2*i]   = __floats2half2_rn(v.x, v.y);
        ((__half2*)g_xh)[2*i+1] = __floats2half2_rn(v.z, v.w);
        s[h] = fmaf(v.x, v.x, fmaf(v.y, v.y, fmaf(v.z, v.z, v.w * v.w)));
    }
    #pragma unroll
    for (int h = 0; h < 2; h++) {
        float t = s[h];
        #pragma unroll
        for (int o = 16; o; o >>= 1) t += __shfl_down_sync(0xffffffffu, t, o);
        if (lane == 0) part[h * 8 + wid] = t;          // warp covers half a row
    }
    __syncthreads();
    if (tid < 8) {
        int row = blockIdx.x * 8 + tid;
        g_sq[row] = part[tid * 2] + part[tid * 2 + 1];
        g_maxenc[row] = 0u;
        g_minenc[row] = 0xFFFFFFFFu;
    }
}

// decode upper-triangle tile index -> (bi, bj)
__device__ __forceinline__ void tile2ij(int tile, int& bi, int& bj) {
    int rem = tile; bi = 0;
    while (rem >= NB - bi) { rem -= NB - bi; bi++; }
    bj = bi + rem;
}

// ---------- 1) fp16 Gram tiles (upper triangle, persistent, prefetch-overlap) ----------
// Tiles: 128 rows x 128B (8 chunks), swizzle ch ^ (row & 7) -> conflict-free ldmatrix.
__global__ void __launch_bounds__(256, 2)
triplet_mma(const int* __restrict__ tgt) {
    extern __shared__ char smem[];
    const uint32_t sb = smem_u32(smem);
    const int tid = threadIdx.x, lane = tid & 31, wid = tid >> 5;
    const int wm = wid >> 2, wn = wid & 3;          // warp tile: rows wm*64, cols wn*32

    auto issue_loads = [&](int i0, int j0, int c, int st) {
        const uint32_t abase = sb + OFF_STAGE + st * STAGE_BYTES;
        const uint32_t bbase = abase + OFF_B;
        const int kb = c * KC;
        #pragma unroll
        for (int t = 0; t < 4; t++) {
            int idx = t * 256 + tid;           // 0..1023
            int row = idx >> 3;                // 0..127
            int ch  = idx & 7;
            uint32_t d = (uint32_t)((ch ^ (row & 7)) * 16);
            const __half* sA = g_xh + (size_t)(i0 + row) * DD + kb + ch * 8;
            const __half* sB = g_xh + (size_t)(j0 + row) * DD + kb + ch * 8;
            CP_ASYNC(abase + row * 128 + d, sA);
            CP_ASYNC(bbase + row * 128 + d, sB);
        }
        CP_COMMIT();
    };

    int bi, bj;
    tile2ij(blockIdx.x, bi, bj);
    if (blockIdx.x < NTILES) issue_loads(bi * TI, bj * TJ, 0, 0);   // prologue prefetch

    for (int tile = blockIdx.x; tile < NTILES; tile += GRID) {
        const int i0 = bi * TI, j0 = bj * TJ;
        const bool diag = (bi == bj);
        int nbi = 0, nbj = 0;
        const bool has_next = (tile + GRID < NTILES);
        if (has_next) tile2ij(tile + GRID, nbi, nbj);

        __syncthreads();   // prev epilogue done before sq/lbl smem rewrite
        if (tid < TJ) {
            ((float*)(smem + OFF_SQJ))[tid] = g_sq[j0 + tid];
            ((int*)(smem + OFF_LBLJ))[tid]  = tgt[j0 + tid];
        } else {
            int r = tid - TJ;
            ((float*)(smem + OFF_SQI))[r] = g_sq[i0 + r];
            ((int*)(smem + OFF_LBLI))[r]  = tgt[i0 + r];
        }

        float acc[4][4][4];
        #pragma unroll
        for (int mt = 0; mt < 4; mt++)
            #pragma unroll
            for (int nt = 0; nt < 4; nt++)
                #pragma unroll
                for (int e = 0; e < 4; e++) acc[mt][nt][e] = 0.f;

        for (int c = 0; c < NCH; c++) {
            if (c + 1 < NCH)   issue_loads(i0, j0, c + 1, (c + 1) & 1);
            else if (has_next) issue_loads(nbi * TI, nbj * TJ, 0, 0);   // cross-tile prefetch
            CP_WAIT(1);
            __syncthreads();

            const uint32_t abase = sb + OFF_STAGE + (c & 1) * STAGE_BYTES;
            const uint32_t bbase = abase + OFF_B;

            #pragma unroll
            for (int ks = 0; ks < 4; ks++) {      // 4 k16 steps per 64-chunk
                uint32_t bh[8];
                #pragma unroll
                for (int p = 0; p < 2; p++) {
                    int nrow = wn * 32 + p * 16 + (lane & 7) + ((lane >> 4) << 3);
                    int ch   = ks * 2 + ((lane >> 3) & 1);
                    uint32_t a_ = bbase + nrow * 128 + (uint32_t)((ch ^ (nrow & 7)) * 16);
                    LDSM4(bh[p*4+0], bh[p*4+1], bh[p*4+2], bh[p*4+3], a_);
                }
                #pragma unroll
                for (int mt = 0; mt < 4; mt++) {
                    int arow = wm * 64 + mt * 16 + (lane & 15);
                    int ch   = ks * 2 + (lane >> 4);
                    uint32_t a_ = abase + arow * 128 + (uint32_t)((ch ^ (arow & 7)) * 16);
                    uint32_t ar[4];
                    LDSM4(ar[0], ar[1], ar[2], ar[3], a_);
                    #pragma unroll
                    for (int nt = 0; nt < 4; nt++) {
                        uint32_t b0 = bh[(nt >> 1) * 4 + (nt & 1) * 2];
                        uint32_t b1 = bh[(nt >> 1) * 4 + (nt & 1) * 2 + 1];
                        MMAH(acc[mt][nt], ar, b0, b1);
                    }
                }
            }
            if (c + 1 < NCH) __syncthreads();   // stage reuse guard
        }

        const float* sSqJ  = (const float*)(smem + OFF_SQJ);
        const int*   sLblJ = (const int*)(smem + OFF_LBLJ);
        const float* sSqI  = (const float*)(smem + OFF_SQI);
        const int*   sLblI = (const int*)(smem + OFF_LBLI);

        // ---- row-side mining: val = sq[j] - 2*dot ----
        #pragma unroll
        for (int mt = 0; mt < 4; mt++) {
            #pragma unroll
            for (int half = 0; half < 2; half++) {
                int li    = wm * 64 + mt * 16 + (lane >> 2) + half * 8;
                int mylbl = sLblI[li];
                float mp = -CUDART_INF_F, mn = CUDART_INF_F;
                #pragma unroll
                for (int nt = 0; nt < 4; nt++) {
                    int jl = wn * 32 + nt * 8 + (lane & 3) * 2;
                    float v0 = fmaf(-2.f, acc[mt][nt][half * 2],     sSqJ[jl]);
                    float v1 = fmaf(-2.f, acc[mt][nt][half * 2 + 1], sSqJ[jl + 1]);
                    if (sLblJ[jl]     == mylbl) mp = fmaxf(mp, v0); else mn = fminf(mn, v0);
                    if (sLblJ[jl + 1] == mylbl) mp = fmaxf(mp, v1); else mn = fminf(mn, v1);
                }
                #pragma unroll
                for (int o = 1; o <= 2; o <<= 1) {
                    mp = fmaxf(mp, __shfl_xor_sync(0xffffffffu, mp, o));
                    mn = fminf(mn, __shfl_xor_sync(0xffffffffu, mn, o));
                }
                if ((lane & 3) == 0) {
                    atomicMax(&g_maxenc[i0 + li], enc_f(mp));
                    atomicMin(&g_minenc[i0 + li], enc_f(mn));
                }
            }
        }

        // ---- col-side mining (off-diag only): val = sq[i] - 2*dot ----
        if (!diag) {
            #pragma unroll
            for (int nt = 0; nt < 4; nt++) {
                #pragma unroll
                for (int e = 0; e < 2; e++) {
                    int lj    = wn * 32 + nt * 8 + (lane & 3) * 2 + e;
                    int jlbl  = sLblJ[lj];
                    float mp = -CUDART_INF_F, mn = CUDART_INF_F;
                    #pragma unroll
                    for (int mt = 0; mt < 4; mt++) {
                        #pragma unroll
                        for (int half = 0; half < 2; half++) {
                            int li = wm * 64 + mt * 16 + (lane >> 2) + half * 8;
                            float v = fmaf(-2.f, acc[mt][nt][half * 2 + e], sSqI[li]);
                            if (sLblI[li] == jlbl) mp = fmaxf(mp, v);
                            else                   mn = fminf(mn, v);
                        }
                    }
                    #pragma unroll
                    for (int o = 4; o <= 16; o <<= 1) {
                        mp = fmaxf(mp, __shfl_xor_sync(0xffffffffu, mp, o));
                        mn = fminf(mn, __shfl_xor_sync(0xffffffffu, mn, o));
                    }
                    if (lane < 4) {
                        atomicMax(&g_maxenc[j0 + lj], enc_f(mp));
                        atomicMin(&g_minenc[j0 + lj], enc_f(mn));
                    }
                }
            }
        }

        bi = nbi; bj = nbj;
    }
}

// ---------- 2) final: decode, loss & precision (shuffle tree) ----------
__global__ void triplet_final(float* __restrict__ out) {
    __shared__ float wl[32], wp[32];
    int tid = threadIdx.x, lane = tid & 31, wid = tid >> 5;
    float lsum = 0.f, pcnt = 0.f;
    for (int i = tid; i < BB; i += 1024) {
        float mp = dec_f(g_maxenc[i]);
        float mn = dec_f(g_minenc[i]);
        float d = mp - mn + MARGIN_F;        // == dist_ap - dist_an + margin
        lsum += (d > 0.f) ? d : 0.f;
        pcnt += (mn > mp) ? 1.f : 0.f;
    }
    #pragma unroll
    for (int o = 16; o; o >>= 1) {
        lsum += __shfl_down_sync(0xffffffffu, lsum, o);
        pcnt += __shfl_down_sync(0xffffffffu, pcnt, o);
    }
    if (lane == 0) { wl[wid] = lsum; wp[wid] = pcnt; }
    __syncthreads();
    if (wid == 0) {
        float l = wl[lane], p = wp[lane];
        #pragma unroll
        for (int o = 16; o; o >>= 1) {
            l += __shfl_down_sync(0xffffffffu, l, o);
            p += __shfl_down_sync(0xffffffffu, p, o);
        }
        if (lane == 0) {
            out[0] = l / (float)BB;
            out[1] = p / (float)BB;
        }
    }
}

extern "C" void kernel_launch(void* const* d_in, const int* in_sizes, int n_in,
                              void* d_out, int out_size) {
    const float* x = (const float*)d_in[0];
    const int*   t = (const int*)d_in[1];   // JAX x64-disabled: int32
    float*       o = (float*)d_out;

    cudaFuncSetAttribute(triplet_mma, cudaFuncAttributeMaxDynamicSharedMemorySize, SMEM_DYN);

    prep_kernel<<<BB * DD / 4 / 512, 256>>>(x);
    triplet_mma<<<GRID, 256, SMEM_DYN>>>(t);
    triplet_final<<<1, 1024>>>(o);
}